// round 4
// baseline (speedup 1.0000x reference)
#include <cuda_runtime.h>

// Dice loss: pred (2,8,128^3) fp32, ref (2,1,128^3) int32 -> scalar fp32.
// Persistent single-wave kernel with register double-buffered prefetch:
// loads for tile t+1 are issued before computing tile t, so DRAM stays busy
// through the argmax/count phase. Atomic-free epilogue: per-block partials,
// last block (ticket) reduces and finalizes.

#define S_VOX (128*128*128)            // 2097152 voxels per batch
#define GROUPS_PER_B (S_VOX / 4)       // 524288 float4-groups per batch
#define CNUM 8
#define BNUM 2
#define TPB 128
#define NBLK 592                       // 148 SMs x 4 blocks
#define HALF (NBLK / 2)                // 296 blocks per batch
#define TILES_PER_B (GROUPS_PER_B / TPB)   // 4096 tiles of 128 groups
#define NCNT 21                        // 7 classes x {inter,psum,rsum}

__device__ int g_partials[NBLK * NCNT];
__device__ unsigned int g_ticket;

__global__ __launch_bounds__(TPB, 4) void dice_fused_kernel(
    const float* __restrict__ pred, const int* __restrict__ ref,
    float* __restrict__ out)
{
    __shared__ int s_cnt[NCNT];
    __shared__ int s_last;
    const int tid = threadIdx.x;
    if (tid < NCNT) s_cnt[tid] = 0;

    const int blk = blockIdx.x;
    const int b   = (blk >= HALF) ? 1 : 0;
    const int lb  = b ? (blk - HALF) : blk;

    const float4* pbase = (const float4*)pred + (size_t)b * CNUM * GROUPS_PER_B;
    const int4*   rbase = (const int4*)ref   + (size_t)b * GROUPS_PER_B;

    // Packed per-thread accumulators: 8 classes x 8-bit counts (max 56 each).
    unsigned long long pac = 0ULL, rac = 0ULL, iac = 0ULL;

    auto LOAD = [&](float4* v, int4& r, int t) {
        const int g = t * TPB + tid;
        #pragma unroll
        for (int c = 0; c < CNUM; ++c)
            v[c] = __ldcs(&pbase[(size_t)c * GROUPS_PER_B + g]);
        r = __ldcs(&rbase[g]);
    };

    auto COMPUTE = [&](const float4* v, const int4& r) {
        // argmax per voxel slot (first-max semantics == jnp.argmax)
        int p0 = 0, p1 = 0, p2 = 0, p3 = 0;
        float m0 = v[0].x, m1 = v[0].y, m2 = v[0].z, m3 = v[0].w;
        #pragma unroll
        for (int c = 1; c < CNUM; ++c) {
            if (v[c].x > m0) { m0 = v[c].x; p0 = c; }
            if (v[c].y > m1) { m1 = v[c].y; p1 = c; }
            if (v[c].z > m2) { m2 = v[c].z; p2 = c; }
            if (v[c].w > m3) { m3 = v[c].w; p3 = c; }
        }
        unsigned long long bp;
        bp = 1ULL << (p0 << 3); pac += bp; if (p0 == r.x) iac += bp;
        rac += 1ULL << (r.x << 3);
        bp = 1ULL << (p1 << 3); pac += bp; if (p1 == r.y) iac += bp;
        rac += 1ULL << (r.y << 3);
        bp = 1ULL << (p2 << 3); pac += bp; if (p2 == r.z) iac += bp;
        rac += 1ULL << (r.z << 3);
        bp = 1ULL << (p3 << 3); pac += bp; if (p3 == r.w) iac += bp;
        rac += 1ULL << (r.w << 3);
    };

    // Double-buffered pipeline over tiles lb, lb+HALF, lb+2*HALF, ...
    {
        float4 va[CNUM]; int4 ra;
        float4 vb[CNUM]; int4 rb;
        int t = lb;
        if (t < TILES_PER_B) {
            LOAD(va, ra, t);
            for (;;) {
                int t2 = t + HALF;
                bool v2 = t2 < TILES_PER_B;
                if (v2) LOAD(vb, rb, t2);
                COMPUTE(va, ra);
                if (!v2) break;
                int t3 = t2 + HALF;
                bool v3 = t3 < TILES_PER_B;
                if (v3) LOAD(va, ra, t3);
                COMPUTE(vb, rb);
                if (!v3) break;
                t = t3;
            }
        }
    }

    __syncthreads();   // s_cnt init visible

    // Unpack classes 1..7 and warp-reduce (constant shifts -> cheap).
    const int lane = tid & 31;
    #pragma unroll
    for (int cls = 1; cls < CNUM; ++cls) {
        int li = (int)((iac >> (cls * 8)) & 0xFF);
        int lp = (int)((pac >> (cls * 8)) & 0xFF);
        int lr = (int)((rac >> (cls * 8)) & 0xFF);
        li = (int)__reduce_add_sync(0xffffffffu, (unsigned)li);
        lp = (int)__reduce_add_sync(0xffffffffu, (unsigned)lp);
        lr = (int)__reduce_add_sync(0xffffffffu, (unsigned)lr);
        if (lane == 0) {
            const int j = (cls - 1) * 3;
            atomicAdd(&s_cnt[j + 0], li);
            atomicAdd(&s_cnt[j + 1], lp);
            atomicAdd(&s_cnt[j + 2], lr);
        }
    }
    __syncthreads();

    // Non-atomic per-block partials.
    if (tid < NCNT) g_partials[blk * NCNT + tid] = s_cnt[tid];

    // Ticket: last block reduces + finalizes.
    if (tid == 0) {
        __threadfence();
        s_last = (atomicAdd(&g_ticket, 1u) == (unsigned)(NBLK - 1)) ? 1 : 0;
    }
    __syncthreads();

    if (s_last) {
        __threadfence();   // acquire: see all blocks' partials

        __shared__ int s_tot[BNUM * NCNT];
        if (tid < BNUM * NCNT) s_tot[tid] = 0;
        __syncthreads();

        int acc0[NCNT], acc1[NCNT];
        #pragma unroll
        for (int j = 0; j < NCNT; ++j) { acc0[j] = 0; acc1[j] = 0; }
        for (int row = tid; row < HALF; row += TPB) {
            #pragma unroll
            for (int j = 0; j < NCNT; ++j)
                acc0[j] += g_partials[row * NCNT + j];
        }
        for (int row = HALF + tid; row < NBLK; row += TPB) {
            #pragma unroll
            for (int j = 0; j < NCNT; ++j)
                acc1[j] += g_partials[row * NCNT + j];
        }
        #pragma unroll
        for (int j = 0; j < NCNT; ++j) {
            int v0 = (int)__reduce_add_sync(0xffffffffu, (unsigned)acc0[j]);
            int v1 = (int)__reduce_add_sync(0xffffffffu, (unsigned)acc1[j]);
            if (lane == 0) {
                if (v0) atomicAdd(&s_tot[j], v0);
                if (v1) atomicAdd(&s_tot[NCNT + j], v1);
            }
        }
        __syncthreads();

        if (tid == 0) {
            float lsum = 0.0f;
            #pragma unroll
            for (int bb = 0; bb < BNUM; ++bb) {
                float dsum = 0.0f, w = 0.0f;
                #pragma unroll
                for (int c = 0; c < CNUM - 1; ++c) {
                    const float inter = (float)s_tot[bb * NCNT + c * 3 + 0];
                    const float psum  = (float)s_tot[bb * NCNT + c * 3 + 1];
                    const float rsum  = (float)s_tot[bb * NCNT + c * 3 + 2];
                    if (rsum > 0.0f) {
                        const float uni = psum + rsum;
                        dsum += 2.0f * inter / (uni > 0.0f ? uni : 1.0f);
                        w += 1.0f;
                    }
                }
                lsum += dsum / w;
            }
            out[0] = lsum / (float)BNUM;
            atomicExch(&g_ticket, 0u);   // reset for next graph replay
        }
    }
}

extern "C" void kernel_launch(void* const* d_in, const int* in_sizes, int n_in,
                              void* d_out, int out_size)
{
    const float* pred = (const float*)d_in[0];
    const int*   ref  = (const int*)d_in[1];
    float*       out  = (float*)d_out;

    dice_fused_kernel<<<NBLK, TPB>>>(pred, ref, out);
}